// round 11
// baseline (speedup 1.0000x reference)
#include <cuda_runtime.h>
#include <math.h>
#include <math_constants.h>
#include <stdint.h>

#define N_SAMP 131072
#define NCH 32
#define NB 4
#define NT 8
#define L_CHUNK 128
#define K_CHUNK 1024           /* biquad chunks: N = 1024*128 */
#define KS_D 10                /* Kogge-Stone rounds: log2(K_CHUNK) */

#define KGRP 32                /* smoother samples per composed group */
#define NGRP (N_SAMP / KGRP)   /* 4096 groups per channel */
#define CLS 33                 /* KGRP+1 affine classes */
#define QU 17                  /* u64 slots per (group,ch): 33 floats + INF pad */
#define TILE_G 16              /* groups per bulk tile */
#define NTILE (NGRP / TILE_G)  /* 256 */
#define TILE_U64 (TILE_G * QU * NCH)   /* 8704 u64 */
#define TILE_BYTES (TILE_U64 * 8)      /* 69632 */
#define NBUF 3
#define SMOOTH_DSMEM (NBUF * TILE_BYTES)  /* 208896 <= 227KB opt-in cap */

struct ChCoef {
    float b0[6], b1[6], b2[6], a1[6], a2[6];
    float4 Ppow[6 * KS_D];     // [stage*KS_D+d] = M^(L_CHUNK*2^d)
    float gain_lin;
    float aa, ar, om_aa, om_ar, sgn;
    float thr, irm1, knee, kq, makeup, cth, sth;
};

__device__ ChCoef d_coef[NCH];
__device__ float  d_xT[NCH * N_SAMP];          // chunk-transposed EQ signal [ch][i][k]
__device__ float  d_xn[NCH * N_SAMP];          // natural [n][ch] EQ signal
__device__ float2 d_uv[NCH * N_SAMP];          // [n][ch] sign-folded (u,v)
__device__ __align__(16) unsigned long long d_comp64[NGRP * QU * NCH]; // intercept pairs
__device__ float  d_gb[NGRP * NCH];            // boundary state h entering group g

__device__ __forceinline__ uint32_t s2u(const void* p) {
    return (uint32_t)__cvta_generic_to_shared(p);
}
__device__ __forceinline__ void mbar_init(uint32_t a, uint32_t cnt) {
    asm volatile("mbarrier.init.shared.b64 [%0], %1;" :: "r"(a), "r"(cnt) : "memory");
}
__device__ __forceinline__ void mbar_expect_tx(uint32_t a, uint32_t bytes) {
    asm volatile("mbarrier.arrive.expect_tx.shared.b64 _, [%0], %1;" :: "r"(a), "r"(bytes) : "memory");
}
__device__ __forceinline__ void bulk_g2s(uint32_t dst, const void* src, uint32_t bytes, uint32_t mbar) {
    asm volatile("cp.async.bulk.shared::cta.global.mbarrier::complete_tx::bytes [%0], [%1], %2, [%3];"
                 :: "r"(dst), "l"(src), "r"(bytes), "r"(mbar) : "memory");
}
__device__ __forceinline__ void mbar_wait(uint32_t mbar, uint32_t parity) {
    asm volatile(
        "{\n\t.reg .pred P;\n"
        "LW_%=:\n\t"
        "mbarrier.try_wait.parity.acquire.cta.shared::cta.b64 P, [%0], %1, 0x989680;\n\t"
        "@P bra LD_%=;\n\t"
        "bra LW_%=;\n"
        "LD_%=:\n\t}"
        :: "r"(mbar), "r"(parity) : "memory");
}
__device__ __forceinline__ uint64_t pack2(float lo, float hi) {
    uint64_t r; asm("mov.b64 %0, {%1,%2};" : "=l"(r) : "f"(lo), "f"(hi)); return r;
}
__device__ __forceinline__ void unpack2(uint64_t v, float& lo, float& hi) {
    asm("mov.b64 {%0,%1}, %2;" : "=f"(lo), "=f"(hi) : "l"(v));
}
__device__ __forceinline__ uint64_t ffma2(uint64_t a, uint64_t b, uint64_t c) {
    uint64_t d; asm("fma.rn.f32x2 %0, %1, %2, %3;" : "=l"(d) : "l"(a), "l"(b), "l"(c)); return d;
}
__device__ __forceinline__ float ex2_approx(float x) {
    float y; asm("ex2.approx.ftz.f32 %0, %1;" : "=f"(y) : "f"(x)); return y;
}

// ---------------------------------------------------------------------------
// A: per-channel coefficient setup (fp64, rounded to fp32)
// ---------------------------------------------------------------------------
__global__ void setup_kernel(const float* __restrict__ params) {
    int ch = threadIdx.x;
    if (ch >= NCH) return;

    const float lo[26] = {-24.f,-20.f,20.f,0.1f,-20.f,80.f,0.1f,-20.f,200.f,0.1f,
                          -20.f,500.f,0.1f,-20.f,1000.f,0.1f,-20.f,4000.f,0.1f,
                          -60.f,1.f,1.f,10.f,0.1f,0.f,0.f};
    const float hi[26] = {24.f,20.f,2000.f,6.f,20.f,2000.f,6.f,20.f,4000.f,6.f,
                          20.f,8000.f,6.f,20.f,12000.f,6.f,20.f,18000.f,6.f,
                          0.f,10.f,100.f,1000.f,24.f,12.f,1.f};
    double p[26];
    for (int j = 0; j < 26; ++j) {
        float v = params[ch * 26 + j] * (hi[j] - lo[j]) + lo[j];
        p[j] = (double)v;
    }

    ChCoef& C = d_coef[ch];
    const double FSd = 44100.0;
    const double PI  = 3.14159265358979323846;

    for (int st = 0; st < 6; ++st) {
        double gdb, f, q; int shelf = 0; double sgn = 1.0;
        if (st == 0)      { gdb = p[1];  f = p[2];  q = p[3];  shelf = 1; sgn =  1.0; }
        else if (st == 5) { gdb = p[16]; f = p[17]; q = p[18]; shelf = 1; sgn = -1.0; }
        else              { gdb = p[1+3*st]; f = p[2+3*st]; q = p[3+3*st]; }

        double A  = pow(10.0, gdb / 40.0);
        double w0 = 2.0 * PI * f / FSd;
        double cw = cos(w0), sw = sin(w0);
        double al = sw / (2.0 * q);
        double bb0, bb1, bb2, aa0, aa1, aa2;
        if (shelf) {
            double s2 = 2.0 * sqrt(A) * al;
            bb0 = A * (A + 1.0 - sgn * (A - 1.0) * cw + s2);
            bb1 = sgn * 2.0 * A * (A - 1.0 - sgn * (A + 1.0) * cw);
            bb2 = A * (A + 1.0 - sgn * (A - 1.0) * cw - s2);
            aa0 = A + 1.0 + sgn * (A - 1.0) * cw + s2;
            aa1 = -sgn * 2.0 * (A - 1.0 + sgn * (A + 1.0) * cw);
            aa2 = A + 1.0 + sgn * (A - 1.0) * cw - s2;
        } else {
            bb0 = 1.0 + al * A; bb1 = -2.0 * cw; bb2 = 1.0 - al * A;
            aa0 = 1.0 + al / A; aa1 = -2.0 * cw; aa2 = 1.0 - al / A;
        }
        double b0 = bb0/aa0, b1 = bb1/aa0, b2 = bb2/aa0, a1 = aa1/aa0, a2 = aa2/aa0;
        C.b0[st]=(float)b0; C.b1[st]=(float)b1; C.b2[st]=(float)b2;
        C.a1[st]=(float)a1; C.a2[st]=(float)a2;

        // M = [[-a1,1],[-a2,0]] from fp32-rounded a1,a2 (matches the sample
        // loops); square 7x -> M^128, then store M^(128*2^d), d=0..KS_D-1.
        double fa1 = (double)C.a1[st], fa2 = (double)C.a2[st];
        double m00=-fa1, m01=1.0, m10=-fa2, m11=0.0;
        for (int s = 0; s < 7; ++s) {
            double n00=m00*m00+m01*m10, n01=m00*m01+m01*m11;
            double n10=m10*m00+m11*m10, n11=m10*m01+m11*m11;
            m00=n00; m01=n01; m10=n10; m11=n11;
        }
        for (int d = 0; d < KS_D; ++d) {
            C.Ppow[st*KS_D+d] = make_float4((float)m00,(float)m01,(float)m10,(float)m11);
            double n00=m00*m00+m01*m10, n01=m00*m01+m01*m11;
            double n10=m10*m00+m11*m10, n11=m10*m01+m11*m11;
            m00=n00; m01=n01; m10=n10; m11=n11;
        }
    }

    C.gain_lin = (float)pow(10.0, p[0] / 20.0);
    double aa = exp(-1000.0 / (FSd * p[21]));
    double ar = exp(-1000.0 / (FSd * p[22]));
    C.aa=(float)aa; C.ar=(float)ar;
    C.om_aa=(float)(1.0-aa); C.om_ar=(float)(1.0-ar);
    C.sgn = (aa <= ar) ? 1.f : -1.f;    // min-form if +1, max folded to min if -1
    C.thr = (float)p[19];
    double irm1 = 1.0 / p[20] - 1.0;
    C.irm1=(float)irm1;
    C.knee=(float)p[23];
    C.kq  =(float)(irm1 / (2.0 * p[23]));
    C.makeup=(float)p[24];
    double th = p[25] * (PI / 2.0);
    C.cth=(float)cos(th); C.sth=(float)sin(th);
}

// ---------------------------------------------------------------------------
// B0: input transpose + gain. tracks[ch][n] (n = k*128+i) -> d_xT[ch][i][k],
// both sides coalesced via 32x32 smem tile. One element per thread.
// ---------------------------------------------------------------------------
__global__ __launch_bounds__(1024) void tin_kernel(const float* __restrict__ tracks) {
    int ch = blockIdx.x >> 7;          // 0..31
    int t  = blockIdx.x & 127;         // 128 tiles per channel
    int i0 = (t & 3) << 5;             // 0,32,64,96
    int k0 = (t >> 2) << 5;            // 0..992 step 32
    int w  = threadIdx.x >> 5;
    int l  = threadIdx.x & 31;
    __shared__ float tile[32][33];

    float gain = d_coef[ch].gain_lin;
    // read element (i = i0+l, k = k0+w): n = (k0+w)*128 + i0+l  -> coalesced in l
    tile[l][w] = gain * tracks[(ch << 17) + ((k0 + w) << 7) + i0 + l];
    __syncthreads();
    // write element (i = i0+w, k = k0+l): xT index (i0+w)*1024 + k0+l -> coalesced in l
    d_xT[(ch << 17) + ((i0 + w) << 10) + k0 + l] = tile[w][l];
}

// ---------------------------------------------------------------------------
// B: 6 biquad stages, exact blocked scan (Kogge-Stone combine). 1 block/channel.
// All phases read/write d_xT coalesced (lanes contiguous in k).
// ---------------------------------------------------------------------------
__global__ __launch_bounds__(K_CHUNK) void biquad_kernel() {
    int ch = blockIdx.x;
    int k  = threadIdx.x;                 // chunk id 0..1023
    __shared__ float2 sbuf[K_CHUNK];

    const ChCoef& C = d_coef[ch];
    float* xT = d_xT + ch * N_SAMP;

    for (int st = 0; st < 6; ++st) {
        float b0=C.b0[st], b1=C.b1[st], b2=C.b2[st], a1=C.a1[st], a2=C.a2[st];

        // phase 1: zero-init chunk run -> q_k (final state of chunk)
        float s1 = 0.f, s2 = 0.f;
        #pragma unroll 8
        for (int i = 0; i < L_CHUNK; ++i) {
            float x = xT[i * K_CHUNK + k];
            float y = fmaf(b0, x, s1);
            float t = fmaf(-a1, y, s2);
            s1 = fmaf(b1, x, t);
            s2 = fmaf(b2, x, -a2 * y);
        }
        sbuf[k] = make_float2(s1, s2);
        __syncthreads();

        // phase 2: Kogge-Stone scan of x_k = q_k + P^(2^d) x_{k-2^d}
        float2 xk = make_float2(s1, s2);
        #pragma unroll
        for (int d = 0; d < KS_D; ++d) {
            int s = 1 << d;
            float2 pv = make_float2(0.f, 0.f);
            bool act = (k >= s);
            if (act) pv = sbuf[k - s];
            __syncthreads();
            if (act) {
                float4 P = C.Ppow[st*KS_D+d];
                xk.x = fmaf(P.x, pv.x, fmaf(P.y, pv.y, xk.x));
                xk.y = fmaf(P.z, pv.x, fmaf(P.w, pv.y, xk.y));
                sbuf[k] = xk;
            }
            __syncthreads();
        }
        float2 G = (k > 0) ? sbuf[k-1] : make_float2(0.f, 0.f);
        __syncthreads();

        // phase 3: rerun from true init, write outputs
        s1 = G.x; s2 = G.y;
        #pragma unroll 8
        for (int i = 0; i < L_CHUNK; ++i) {
            float x = xT[i * K_CHUNK + k];
            float y = fmaf(b0, x, s1);
            float t = fmaf(-a1, y, s2);
            s1 = fmaf(b1, x, t);
            s2 = fmaf(b2, x, -a2 * y);
            xT[i * K_CHUNK + k] = y;
        }
        __syncthreads();
    }
}

// ---------------------------------------------------------------------------
// C: transpose + gain-computer. Reads d_xT [ch][i<128][k<1024],
// writes d_xn[n][ch], d_uv[n][ch] with n = k*128 + i.
// ---------------------------------------------------------------------------
__global__ __launch_bounds__(1024) void prep_kernel() {
    int i  = blockIdx.x >> 5;          // 0..127
    int k0 = (blockIdx.x & 31) << 5;   // 0,32,...,992
    int w  = threadIdx.x >> 5;
    int l  = threadIdx.x & 31;
    __shared__ float tile[32][33];

    tile[l][w] = d_xT[(w << 17) + (i << 10) + k0 + l];  // ch=w, k=k0+l (coalesced)
    __syncthreads();

    float x = tile[w][l];                                // k=k0+w, ch=l
    const ChCoef& C = d_coef[l];
    float d = fmaf(6.0205999132796239f, __log2f(fmaxf(fabsf(x), 1e-8f)), -C.thr);
    float two_d = 2.f * d;
    float gc;
    if (two_d < -C.knee)      gc = 0.f;
    else if (two_d > C.knee)  gc = d * C.irm1;
    else { float hh = d + 0.5f * C.knee; gc = C.kq * hh * hh; }
    float s = C.sgn;
    int n = ((k0 + w) << 7) + i;
    d_uv[n * 32 + l] = make_float2(s * C.om_aa * gc, s * C.om_ar * gc);
    d_xn[n * 32 + l] = x;
}

// ---------------------------------------------------------------------------
// D: compose KGRP affine-min steps per group -> CLS intercepts. Thread = (g,ch).
// Invariant after s steps: h -> min_{j=0..s} (aa^j ar^{s-j} h + c[j]).
// ---------------------------------------------------------------------------
__global__ __launch_bounds__(256) void compose_kernel() {
    int idx = blockIdx.x * blockDim.x + threadIdx.x;
    int g = idx >> 5, ch = idx & 31;
    const ChCoef& C = d_coef[ch];
    float aa = C.aa, ar = C.ar;
    int n0 = g * KGRP;

    float c[CLS];
    float2 e = d_uv[n0 * 32 + ch];
    c[1] = e.x;            // one attack step (slope aa)
    c[0] = e.y;            // one release step (slope ar)
    #pragma unroll
    for (int s = 1; s < KGRP; ++s) {
        float2 wv = d_uv[(n0 + s) * 32 + ch];
        float u = wv.x, v = wv.y;
        c[s+1] = fmaf(aa, c[s], u);
        #pragma unroll
        for (int j = s; j >= 1; --j)
            c[j] = fminf(fmaf(ar, c[j], v), fmaf(aa, c[j-1], u));
        c[0] = fmaf(ar, c[0], v);
    }
    float2* dst = (float2*)&d_comp64[(size_t)g * (QU * 32) + ch];
    #pragma unroll
    for (int q = 0; q < 16; ++q)
        dst[q * 32] = make_float2(c[2*q], c[2*q+1]);
    dst[16 * 32] = make_float2(c[32], CUDART_INF_F);
}

// ---------------------------------------------------------------------------
// E: serial smoother over composed groups. 1 warp, lane = channel.
// Triple-buffered cp.async.bulk tiles in dynamic smem (2 copies in flight,
// each with ~2 tiles of compute time to land); FFMA2-packed evaluate.
// ---------------------------------------------------------------------------
__global__ void __launch_bounds__(32, 1) smooth_serial() {
    extern __shared__ __align__(16) unsigned long long dynbuf[];
    __shared__ __align__(8) unsigned long long mbar[NBUF];

    int ch = threadIdx.x;
    const ChCoef& C = d_coef[ch];
    float aa = C.aa, ar = C.ar;
    float Sv[CLS];
    {
        float av = 1.f;
        float rvp[CLS];
        rvp[0] = 1.f;
        #pragma unroll
        for (int j = 1; j < CLS; ++j) rvp[j] = rvp[j-1] * ar;
        #pragma unroll
        for (int j = 0; j < CLS; ++j) { Sv[j] = av * rvp[KGRP - j]; av *= aa; }
    }
    uint64_t S2[QU];
    #pragma unroll
    for (int q = 0; q < 16; ++q) S2[q] = pack2(Sv[2*q], Sv[2*q+1]);
    S2[16] = pack2(Sv[32], 0.f);       // hi: 0*h + INF = INF, ignored by min

    uint32_t mb[NBUF];
    #pragma unroll
    for (int j = 0; j < NBUF; ++j) mb[j] = s2u(&mbar[j]);
    if (ch == 0) {
        #pragma unroll
        for (int j = 0; j < NBUF; ++j) mbar_init(mb[j], 1);
    }
    asm volatile("fence.proxy.async.shared::cta;" ::: "memory");
    __syncwarp();

    const unsigned long long* src = d_comp64;
    if (ch == 0) {
        #pragma unroll
        for (int j = 0; j < NBUF; ++j) {
            mbar_expect_tx(mb[j], TILE_BYTES);
            bulk_g2s(s2u(&dynbuf[(size_t)j * TILE_U64]), src + (size_t)j * TILE_U64,
                     TILE_BYTES, mb[j]);
        }
    }

    float h = 0.f;
    float* gb = d_gb + ch;
    for (int t = 0; t < NTILE; ++t) {
        int b  = t % NBUF;
        int ph = (t / NBUF) & 1;
        mbar_wait(mb[b], ph);
        const uint64_t* sb64 = (const uint64_t*)(dynbuf + (size_t)b * TILE_U64);
        #pragma unroll 4
        for (int gg = 0; gg < TILE_G; ++gg) {
            int base = gg * (QU * 32) + ch;
            gb[(t * TILE_G + gg) * 32] = h;
            uint64_t hh = pack2(h, h);
            uint64_t qv[QU];
            #pragma unroll
            for (int q = 0; q < QU; ++q)
                qv[q] = ffma2(S2[q], hh, sb64[base + q * 32]);
            float r[2*QU];
            #pragma unroll
            for (int q = 0; q < QU; ++q) unpack2(qv[q], r[2*q], r[2*q+1]);
            float m[QU];
            #pragma unroll
            for (int q = 0; q < QU; ++q) m[q] = fminf(r[2*q], r[2*q+1]);
            float a0 = fminf(m[0],  m[1]),  a1 = fminf(m[2],  m[3]);
            float a2 = fminf(m[4],  m[5]),  a3 = fminf(m[6],  m[7]);
            float a4 = fminf(m[8],  m[9]),  a5 = fminf(m[10], m[11]);
            float a6 = fminf(m[12], m[13]), a7 = fminf(m[14], m[15]);
            a0 = fminf(a0, a1); a2 = fminf(a2, a3);
            a4 = fminf(a4, a5); a6 = fminf(a6, a7);
            a0 = fminf(a0, a2); a4 = fminf(a4, a6);
            h = fminf(fminf(a0, a4), m[16]);
        }
        if (t + NBUF < NTILE) {
            __syncwarp();
            asm volatile("fence.proxy.async.shared::cta;" ::: "memory");
            if (ch == 0) {
                mbar_expect_tx(mb[b], TILE_BYTES);
                bulk_g2s(s2u(&dynbuf[(size_t)b * TILE_U64]),
                         src + (size_t)(t + NBUF) * TILE_U64, TILE_BYTES, mb[b]);
            }
        }
    }
}

// ---------------------------------------------------------------------------
// F: fused fill+output. Thread = (group g, batch b). Re-runs the 32-sample
// smoother recurrence for the batch's 8 channels in registers, applies
// makeup/pan, writes (B, 2, N) output directly. Vectorized float4 loads,
// unrolled x4 for memory-level parallelism.
// ---------------------------------------------------------------------------
__global__ __launch_bounds__(256) void finish_kernel(float* __restrict__ out) {
    int idx = blockIdx.x * blockDim.x + threadIdx.x;   // over NGRP * NB
    if (idx >= NGRP * NB) return;
    int g = idx >> 2, b = idx & 3;
    int c0 = b * 8;

    float h[8], aa[8], ar[8], sg[8], mkc[8], ct[8], st[8];
    #pragma unroll
    for (int t = 0; t < 8; ++t) {
        const ChCoef& C = d_coef[c0 + t];
        aa[t] = C.aa; ar[t] = C.ar;
        sg[t] = C.sgn * 0.16609640474436813f;           // sgn * log2(10)/20
        mkc[t] = C.makeup * 0.16609640474436813f;
        ct[t] = C.cth; st[t] = C.sth;
        h[t] = d_gb[g * 32 + c0 + t];
    }
    int n0 = g * KGRP;
    float* outL = out + (b << 18);
    float* outR = outL + N_SAMP;
    #pragma unroll 4
    for (int i = 0; i < KGRP; ++i) {
        int n = n0 + i;
        const float4* uvp4 = (const float4*)&d_uv[n * 32 + c0];   // 4x float4 = 8 float2
        const float4* xp4  = (const float4*)&d_xn[n * 32 + c0];   // 2x float4 = 8 float
        float4 uva = uvp4[0], uvb = uvp4[1], uvc = uvp4[2], uvd = uvp4[3];
        float4 xa  = xp4[0],  xb  = xp4[1];
        float ux[8] = {uva.x, uva.z, uvb.x, uvb.z, uvc.x, uvc.z, uvd.x, uvd.z};
        float vy[8] = {uva.y, uva.w, uvb.y, uvb.w, uvc.y, uvc.w, uvd.y, uvd.w};
        float xs[8] = {xa.x, xa.y, xa.z, xa.w, xb.x, xb.y, xb.z, xb.w};
        float sl = 0.f, sr = 0.f;
        #pragma unroll
        for (int t = 0; t < 8; ++t) {
            h[t] = fminf(fmaf(aa[t], h[t], ux[t]), fmaf(ar[t], h[t], vy[t]));
            float sc = ex2_approx(fmaf(sg[t], h[t], mkc[t]));
            float y = xs[t] * sc;
            sl = fmaf(ct[t], y, sl);
            sr = fmaf(st[t], y, sr);
        }
        outL[n] = sl;
        outR[n] = sr;
    }
}

// ---------------------------------------------------------------------------
extern "C" void kernel_launch(void* const* d_in, const int* in_sizes, int n_in,
                              void* d_out, int out_size) {
    const float* tracks = (const float*)d_in[0];
    const float* params = (const float*)d_in[1];
    if (n_in >= 2 && in_sizes[0] == NB * NT * 26) {
        params = (const float*)d_in[0];
        tracks = (const float*)d_in[1];
    }
    cudaFuncSetAttribute(smooth_serial,
                         cudaFuncAttributeMaxDynamicSharedMemorySize, SMOOTH_DSMEM);
    setup_kernel<<<1, 32>>>(params);
    tin_kernel<<<NCH * 128, 1024>>>(tracks);
    biquad_kernel<<<NCH, K_CHUNK>>>();
    prep_kernel<<<4096, 1024>>>();
    compose_kernel<<<(NGRP * NCH) / 256, 256>>>();
    smooth_serial<<<1, 32, SMOOTH_DSMEM>>>();
    finish_kernel<<<(NGRP * NB + 255) / 256, 256>>>((float*)d_out);
}

// round 13
// speedup vs baseline: 1.0799x; 1.0799x over previous
#include <cuda_runtime.h>
#include <math.h>
#include <math_constants.h>
#include <stdint.h>

#define N_SAMP 131072
#define NCH 32
#define NB 4
#define NT 8
#define L_CHUNK 128
#define K_CHUNK 1024           /* biquad chunks: N = 1024*128 */
#define KS_D 10                /* Kogge-Stone rounds: log2(K_CHUNK) */

#define KGRP 32                /* smoother samples per composed group */
#define NGRP (N_SAMP / KGRP)   /* 4096 groups per channel */
#define CLS 33                 /* KGRP+1 affine classes */
#define QU 17                  /* u64 slots per (group,ch): 33 floats + INF pad */
#define TILE_G 16              /* groups per bulk tile */
#define NTILE (NGRP / TILE_G)  /* 256 */
#define TILE_U64 (TILE_G * QU * NCH)   /* 8704 u64 */
#define TILE_BYTES (TILE_U64 * 8)      /* 69632 */
#define NBUF 3
#define SMOOTH_DSMEM (NBUF * TILE_BYTES)  /* 208896 <= 227KB opt-in cap */

struct ChCoef {
    float b0[6], b1[6], b2[6], a1[6], a2[6];
    float4 Ppow[6 * KS_D];     // [stage*KS_D+d] = M^(L_CHUNK*2^d)
    float gain_lin;
    float aa, ar, om_aa, om_ar, sgn;
    float thr, irm1, knee, kq, makeup, cth, sth;
};

__device__ ChCoef d_coef[NCH];
__device__ float  d_xT[NCH * N_SAMP];          // chunk-transposed EQ signal [ch][i][k]
__device__ float  d_xn[NCH * N_SAMP];          // natural [n][ch] EQ signal
__device__ float2 d_uv[NCH * N_SAMP];          // [n][ch] sign-folded (u,v)
__device__ __align__(16) unsigned long long d_comp64[NGRP * QU * NCH]; // intercept pairs
__device__ float  d_gb[NGRP * NCH];            // boundary state h entering group g

__device__ __forceinline__ uint32_t s2u(const void* p) {
    return (uint32_t)__cvta_generic_to_shared(p);
}
__device__ __forceinline__ void mbar_init(uint32_t a, uint32_t cnt) {
    asm volatile("mbarrier.init.shared.b64 [%0], %1;" :: "r"(a), "r"(cnt) : "memory");
}
__device__ __forceinline__ void mbar_expect_tx(uint32_t a, uint32_t bytes) {
    asm volatile("mbarrier.arrive.expect_tx.shared.b64 _, [%0], %1;" :: "r"(a), "r"(bytes) : "memory");
}
__device__ __forceinline__ void bulk_g2s(uint32_t dst, const void* src, uint32_t bytes, uint32_t mbar) {
    asm volatile("cp.async.bulk.shared::cta.global.mbarrier::complete_tx::bytes [%0], [%1], %2, [%3];"
                 :: "r"(dst), "l"(src), "r"(bytes), "r"(mbar) : "memory");
}
__device__ __forceinline__ void mbar_wait(uint32_t mbar, uint32_t parity) {
    asm volatile(
        "{\n\t.reg .pred P;\n"
        "LW_%=:\n\t"
        "mbarrier.try_wait.parity.acquire.cta.shared::cta.b64 P, [%0], %1, 0x989680;\n\t"
        "@P bra LD_%=;\n\t"
        "bra LW_%=;\n"
        "LD_%=:\n\t}"
        :: "r"(mbar), "r"(parity) : "memory");
}
__device__ __forceinline__ uint64_t pack2(float lo, float hi) {
    uint64_t r; asm("mov.b64 %0, {%1,%2};" : "=l"(r) : "f"(lo), "f"(hi)); return r;
}
__device__ __forceinline__ void unpack2(uint64_t v, float& lo, float& hi) {
    asm("mov.b64 {%0,%1}, %2;" : "=f"(lo), "=f"(hi) : "l"(v));
}
__device__ __forceinline__ uint64_t ffma2(uint64_t a, uint64_t b, uint64_t c) {
    uint64_t d; asm("fma.rn.f32x2 %0, %1, %2, %3;" : "=l"(d) : "l"(a), "l"(b), "l"(c)); return d;
}
__device__ __forceinline__ float ex2_approx(float x) {
    float y; asm("ex2.approx.ftz.f32 %0, %1;" : "=f"(y) : "f"(x)); return y;
}

// ---------------------------------------------------------------------------
// A: per-channel coefficient setup (fp64, rounded to fp32)
// ---------------------------------------------------------------------------
__global__ void setup_kernel(const float* __restrict__ params) {
    int ch = threadIdx.x;
    if (ch >= NCH) return;

    const float lo[26] = {-24.f,-20.f,20.f,0.1f,-20.f,80.f,0.1f,-20.f,200.f,0.1f,
                          -20.f,500.f,0.1f,-20.f,1000.f,0.1f,-20.f,4000.f,0.1f,
                          -60.f,1.f,1.f,10.f,0.1f,0.f,0.f};
    const float hi[26] = {24.f,20.f,2000.f,6.f,20.f,2000.f,6.f,20.f,4000.f,6.f,
                          20.f,8000.f,6.f,20.f,12000.f,6.f,20.f,18000.f,6.f,
                          0.f,10.f,100.f,1000.f,24.f,12.f,1.f};
    double p[26];
    for (int j = 0; j < 26; ++j) {
        float v = params[ch * 26 + j] * (hi[j] - lo[j]) + lo[j];
        p[j] = (double)v;
    }

    ChCoef& C = d_coef[ch];
    const double FSd = 44100.0;
    const double PI  = 3.14159265358979323846;

    for (int st = 0; st < 6; ++st) {
        double gdb, f, q; int shelf = 0; double sgn = 1.0;
        if (st == 0)      { gdb = p[1];  f = p[2];  q = p[3];  shelf = 1; sgn =  1.0; }
        else if (st == 5) { gdb = p[16]; f = p[17]; q = p[18]; shelf = 1; sgn = -1.0; }
        else              { gdb = p[1+3*st]; f = p[2+3*st]; q = p[3+3*st]; }

        double A  = pow(10.0, gdb / 40.0);
        double w0 = 2.0 * PI * f / FSd;
        double cw = cos(w0), sw = sin(w0);
        double al = sw / (2.0 * q);
        double bb0, bb1, bb2, aa0, aa1, aa2;
        if (shelf) {
            double s2 = 2.0 * sqrt(A) * al;
            bb0 = A * (A + 1.0 - sgn * (A - 1.0) * cw + s2);
            bb1 = sgn * 2.0 * A * (A - 1.0 - sgn * (A + 1.0) * cw);
            bb2 = A * (A + 1.0 - sgn * (A - 1.0) * cw - s2);
            aa0 = A + 1.0 + sgn * (A - 1.0) * cw + s2;
            aa1 = -sgn * 2.0 * (A - 1.0 + sgn * (A + 1.0) * cw);
            aa2 = A + 1.0 + sgn * (A - 1.0) * cw - s2;
        } else {
            bb0 = 1.0 + al * A; bb1 = -2.0 * cw; bb2 = 1.0 - al * A;
            aa0 = 1.0 + al / A; aa1 = -2.0 * cw; aa2 = 1.0 - al / A;
        }
        double b0 = bb0/aa0, b1 = bb1/aa0, b2 = bb2/aa0, a1 = aa1/aa0, a2 = aa2/aa0;
        C.b0[st]=(float)b0; C.b1[st]=(float)b1; C.b2[st]=(float)b2;
        C.a1[st]=(float)a1; C.a2[st]=(float)a2;

        double fa1 = (double)C.a1[st], fa2 = (double)C.a2[st];
        double m00=-fa1, m01=1.0, m10=-fa2, m11=0.0;
        for (int s = 0; s < 7; ++s) {
            double n00=m00*m00+m01*m10, n01=m00*m01+m01*m11;
            double n10=m10*m00+m11*m10, n11=m10*m01+m11*m11;
            m00=n00; m01=n01; m10=n10; m11=n11;
        }
        for (int d = 0; d < KS_D; ++d) {
            C.Ppow[st*KS_D+d] = make_float4((float)m00,(float)m01,(float)m10,(float)m11);
            double n00=m00*m00+m01*m10, n01=m00*m01+m01*m11;
            double n10=m10*m00+m11*m10, n11=m10*m01+m11*m11;
            m00=n00; m01=n01; m10=n10; m11=n11;
        }
    }

    C.gain_lin = (float)pow(10.0, p[0] / 20.0);
    double aa = exp(-1000.0 / (FSd * p[21]));
    double ar = exp(-1000.0 / (FSd * p[22]));
    C.aa=(float)aa; C.ar=(float)ar;
    C.om_aa=(float)(1.0-aa); C.om_ar=(float)(1.0-ar);
    C.sgn = (aa <= ar) ? 1.f : -1.f;    // min-form if +1, max folded to min if -1
    C.thr = (float)p[19];
    double irm1 = 1.0 / p[20] - 1.0;
    C.irm1=(float)irm1;
    C.knee=(float)p[23];
    C.kq  =(float)(irm1 / (2.0 * p[23]));
    C.makeup=(float)p[24];
    double th = p[25] * (PI / 2.0);
    C.cth=(float)cos(th); C.sth=(float)sin(th);
}

// ---------------------------------------------------------------------------
// B0: input transpose + gain. tracks[ch][n] (n = k*128+i) -> d_xT[ch][i][k],
// both sides coalesced via 32x32 smem tile. One element per thread.
// ---------------------------------------------------------------------------
__global__ __launch_bounds__(1024) void tin_kernel(const float* __restrict__ tracks) {
    int ch = blockIdx.x >> 7;          // 0..31
    int t  = blockIdx.x & 127;         // 128 tiles per channel
    int i0 = (t & 3) << 5;             // 0,32,64,96
    int k0 = (t >> 2) << 5;            // 0..992 step 32
    int w  = threadIdx.x >> 5;
    int l  = threadIdx.x & 31;
    __shared__ float tile[32][33];

    float gain = d_coef[ch].gain_lin;
    tile[l][w] = gain * tracks[(ch << 17) + ((k0 + w) << 7) + i0 + l];
    __syncthreads();
    d_xT[(ch << 17) + ((i0 + w) << 10) + k0 + l] = tile[w][l];
}

// ---------------------------------------------------------------------------
// B: 6 biquad stages, exact blocked scan (Kogge-Stone combine). 1 block/channel.
// ---------------------------------------------------------------------------
__global__ __launch_bounds__(K_CHUNK) void biquad_kernel() {
    int ch = blockIdx.x;
    int k  = threadIdx.x;                 // chunk id 0..1023
    __shared__ float2 sbuf[K_CHUNK];

    const ChCoef& C = d_coef[ch];
    float* xT = d_xT + ch * N_SAMP;

    for (int st = 0; st < 6; ++st) {
        float b0=C.b0[st], b1=C.b1[st], b2=C.b2[st], a1=C.a1[st], a2=C.a2[st];

        // phase 1: zero-init chunk run -> q_k
        float s1 = 0.f, s2 = 0.f;
        #pragma unroll 8
        for (int i = 0; i < L_CHUNK; ++i) {
            float x = xT[i * K_CHUNK + k];
            float y = fmaf(b0, x, s1);
            float t = fmaf(-a1, y, s2);
            s1 = fmaf(b1, x, t);
            s2 = fmaf(b2, x, -a2 * y);
        }
        sbuf[k] = make_float2(s1, s2);
        __syncthreads();

        // phase 2: Kogge-Stone scan of x_k = q_k + P^(2^d) x_{k-2^d}
        float2 xk = make_float2(s1, s2);
        #pragma unroll
        for (int d = 0; d < KS_D; ++d) {
            int s = 1 << d;
            float2 pv = make_float2(0.f, 0.f);
            bool act = (k >= s);
            if (act) pv = sbuf[k - s];
            __syncthreads();
            if (act) {
                float4 P = C.Ppow[st*KS_D+d];
                xk.x = fmaf(P.x, pv.x, fmaf(P.y, pv.y, xk.x));
                xk.y = fmaf(P.z, pv.x, fmaf(P.w, pv.y, xk.y));
                sbuf[k] = xk;
            }
            __syncthreads();
        }
        float2 G = (k > 0) ? sbuf[k-1] : make_float2(0.f, 0.f);
        __syncthreads();

        // phase 3: rerun from true init, write outputs
        s1 = G.x; s2 = G.y;
        #pragma unroll 8
        for (int i = 0; i < L_CHUNK; ++i) {
            float x = xT[i * K_CHUNK + k];
            float y = fmaf(b0, x, s1);
            float t = fmaf(-a1, y, s2);
            s1 = fmaf(b1, x, t);
            s2 = fmaf(b2, x, -a2 * y);
            xT[i * K_CHUNK + k] = y;
        }
        __syncthreads();
    }
}

// ---------------------------------------------------------------------------
// C: transpose + gain-computer, 4 elements per thread (MLP=4, 3.5 waves).
// Reads d_xT [ch][i<128][k<1024], writes d_xn[n][ch], d_uv[n][ch], n=k*128+i.
// ---------------------------------------------------------------------------
__global__ __launch_bounds__(1024) void prep_kernel() {
    int iq = blockIdx.x >> 5;          // 0..31  -> i = iq*4 + s
    int k0 = (blockIdx.x & 31) << 5;   // 0,32,...,992
    int w  = threadIdx.x >> 5;
    int l  = threadIdx.x & 31;
    __shared__ float tile[4][32][33];

    #pragma unroll
    for (int s = 0; s < 4; ++s)
        tile[s][l][w] = d_xT[(w << 17) + ((iq * 4 + s) << 10) + k0 + l];
    __syncthreads();

    const ChCoef& C = d_coef[l];
    float sg = C.sgn;
    #pragma unroll
    for (int s = 0; s < 4; ++s) {
        float x = tile[s][w][l];                         // k=k0+w, ch=l
        float d = fmaf(6.0205999132796239f, __log2f(fmaxf(fabsf(x), 1e-8f)), -C.thr);
        float two_d = 2.f * d;
        float gc;
        if (two_d < -C.knee)      gc = 0.f;
        else if (two_d > C.knee)  gc = d * C.irm1;
        else { float hh = d + 0.5f * C.knee; gc = C.kq * hh * hh; }
        int n = ((k0 + w) << 7) + iq * 4 + s;
        d_uv[n * 32 + l] = make_float2(sg * C.om_aa * gc, sg * C.om_ar * gc);
        d_xn[n * 32 + l] = x;
    }
}

// ---------------------------------------------------------------------------
// D: compose KGRP affine-min steps per group -> CLS intercepts. Thread = (g,ch).
// ---------------------------------------------------------------------------
__global__ __launch_bounds__(256) void compose_kernel() {
    int idx = blockIdx.x * blockDim.x + threadIdx.x;
    int g = idx >> 5, ch = idx & 31;
    const ChCoef& C = d_coef[ch];
    float aa = C.aa, ar = C.ar;
    int n0 = g * KGRP;

    float c[CLS];
    float2 e = d_uv[n0 * 32 + ch];
    c[1] = e.x;
    c[0] = e.y;
    #pragma unroll
    for (int s = 1; s < KGRP; ++s) {
        float2 wv = d_uv[(n0 + s) * 32 + ch];
        float u = wv.x, v = wv.y;
        c[s+1] = fmaf(aa, c[s], u);
        #pragma unroll
        for (int j = s; j >= 1; --j)
            c[j] = fminf(fmaf(ar, c[j], v), fmaf(aa, c[j-1], u));
        c[0] = fmaf(ar, c[0], v);
    }
    float2* dst = (float2*)&d_comp64[(size_t)g * (QU * 32) + ch];
    #pragma unroll
    for (int q = 0; q < 16; ++q)
        dst[q * 32] = make_float2(c[2*q], c[2*q+1]);
    dst[16 * 32] = make_float2(c[32], CUDART_INF_F);
}

// ---------------------------------------------------------------------------
// E: serial smoother over composed groups. 1 warp, lane = channel.
// Triple-buffered cp.async.bulk; interleaved ffma2->unpack->min (low regs).
// ---------------------------------------------------------------------------
__global__ void __launch_bounds__(32, 1) smooth_serial() {
    extern __shared__ __align__(16) unsigned long long dynbuf[];
    __shared__ __align__(8) unsigned long long mbar[NBUF];

    int ch = threadIdx.x;
    const ChCoef& C = d_coef[ch];
    float aa = C.aa, ar = C.ar;
    float Sv[CLS];
    {
        float av = 1.f;
        float rvp[CLS];
        rvp[0] = 1.f;
        #pragma unroll
        for (int j = 1; j < CLS; ++j) rvp[j] = rvp[j-1] * ar;
        #pragma unroll
        for (int j = 0; j < CLS; ++j) { Sv[j] = av * rvp[KGRP - j]; av *= aa; }
    }
    uint64_t S2[QU];
    #pragma unroll
    for (int q = 0; q < 16; ++q) S2[q] = pack2(Sv[2*q], Sv[2*q+1]);
    S2[16] = pack2(Sv[32], 0.f);       // hi: 0*h + INF = INF, ignored by min

    uint32_t mb[NBUF];
    #pragma unroll
    for (int j = 0; j < NBUF; ++j) mb[j] = s2u(&mbar[j]);
    if (ch == 0) {
        #pragma unroll
        for (int j = 0; j < NBUF; ++j) mbar_init(mb[j], 1);
    }
    asm volatile("fence.proxy.async.shared::cta;" ::: "memory");
    __syncwarp();

    const unsigned long long* src = d_comp64;
    if (ch == 0) {
        #pragma unroll
        for (int j = 0; j < NBUF; ++j) {
            mbar_expect_tx(mb[j], TILE_BYTES);
            bulk_g2s(s2u(&dynbuf[(size_t)j * TILE_U64]), src + (size_t)j * TILE_U64,
                     TILE_BYTES, mb[j]);
        }
    }

    float h = 0.f;
    float* gb = d_gb + ch;
    for (int t = 0; t < NTILE; ++t) {
        int b  = t % NBUF;
        int ph = (t / NBUF) & 1;
        mbar_wait(mb[b], ph);
        const uint64_t* sb64 = (const uint64_t*)(dynbuf + (size_t)b * TILE_U64);
        #pragma unroll 4
        for (int gg = 0; gg < TILE_G; ++gg) {
            int base = gg * (QU * 32) + ch;
            gb[(t * TILE_G + gg) * 32] = h;
            uint64_t hh = pack2(h, h);
            // interleaved evaluate: ffma2 -> unpack -> pair-min per class pair
            float m[QU];
            #pragma unroll
            for (int q = 0; q < QU; ++q) {
                uint64_t qv = ffma2(S2[q], hh, sb64[base + q * 32]);
                float lo, hi2;
                unpack2(qv, lo, hi2);
                m[q] = fminf(lo, hi2);
            }
            float a0 = fminf(m[0],  m[1]),  a1 = fminf(m[2],  m[3]);
            float a2 = fminf(m[4],  m[5]),  a3 = fminf(m[6],  m[7]);
            float a4 = fminf(m[8],  m[9]),  a5 = fminf(m[10], m[11]);
            float a6 = fminf(m[12], m[13]), a7 = fminf(m[14], m[15]);
            a0 = fminf(a0, a1); a2 = fminf(a2, a3);
            a4 = fminf(a4, a5); a6 = fminf(a6, a7);
            a0 = fminf(a0, a2); a4 = fminf(a4, a6);
            h = fminf(fminf(a0, a4), m[16]);
        }
        if (t + NBUF < NTILE) {
            __syncwarp();
            asm volatile("fence.proxy.async.shared::cta;" ::: "memory");
            if (ch == 0) {
                mbar_expect_tx(mb[b], TILE_BYTES);
                bulk_g2s(s2u(&dynbuf[(size_t)b * TILE_U64]),
                         src + (size_t)(t + NBUF) * TILE_U64, TILE_BYTES, mb[b]);
            }
        }
    }
}

// ---------------------------------------------------------------------------
// F: fused fill+output. Thread = (group g, batch b). Re-runs the 32-sample
// smoother recurrence for 8 channels in registers, applies makeup/pan,
// writes (B, 2, N) output. float4 loads, unrolled x4.
// ---------------------------------------------------------------------------
__global__ __launch_bounds__(256) void finish_kernel(float* __restrict__ out) {
    int idx = blockIdx.x * blockDim.x + threadIdx.x;   // over NGRP * NB
    if (idx >= NGRP * NB) return;
    int g = idx >> 2, b = idx & 3;
    int c0 = b * 8;

    float h[8], aa[8], ar[8], sg[8], mkc[8], ct[8], st[8];
    #pragma unroll
    for (int t = 0; t < 8; ++t) {
        const ChCoef& C = d_coef[c0 + t];
        aa[t] = C.aa; ar[t] = C.ar;
        sg[t] = C.sgn * 0.16609640474436813f;           // sgn * log2(10)/20
        mkc[t] = C.makeup * 0.16609640474436813f;
        ct[t] = C.cth; st[t] = C.sth;
        h[t] = d_gb[g * 32 + c0 + t];
    }
    int n0 = g * KGRP;
    float* outL = out + (b << 18);
    float* outR = outL + N_SAMP;
    #pragma unroll 4
    for (int i = 0; i < KGRP; ++i) {
        int n = n0 + i;
        const float4* uvp4 = (const float4*)&d_uv[n * 32 + c0];
        const float4* xp4  = (const float4*)&d_xn[n * 32 + c0];
        float4 uva = uvp4[0], uvb = uvp4[1], uvc = uvp4[2], uvd = uvp4[3];
        float4 xa  = xp4[0],  xb  = xp4[1];
        float ux[8] = {uva.x, uva.z, uvb.x, uvb.z, uvc.x, uvc.z, uvd.x, uvd.z};
        float vy[8] = {uva.y, uva.w, uvb.y, uvb.w, uvc.y, uvc.w, uvd.y, uvd.w};
        float xs[8] = {xa.x, xa.y, xa.z, xa.w, xb.x, xb.y, xb.z, xb.w};
        float sl = 0.f, sr = 0.f;
        #pragma unroll
        for (int t = 0; t < 8; ++t) {
            h[t] = fminf(fmaf(aa[t], h[t], ux[t]), fmaf(ar[t], h[t], vy[t]));
            float sc = ex2_approx(fmaf(sg[t], h[t], mkc[t]));
            float y = xs[t] * sc;
            sl = fmaf(ct[t], y, sl);
            sr = fmaf(st[t], y, sr);
        }
        outL[n] = sl;
        outR[n] = sr;
    }
}

// ---------------------------------------------------------------------------
extern "C" void kernel_launch(void* const* d_in, const int* in_sizes, int n_in,
                              void* d_out, int out_size) {
    const float* tracks = (const float*)d_in[0];
    const float* params = (const float*)d_in[1];
    if (n_in >= 2 && in_sizes[0] == NB * NT * 26) {
        params = (const float*)d_in[0];
        tracks = (const float*)d_in[1];
    }
    cudaFuncSetAttribute(smooth_serial,
                         cudaFuncAttributeMaxDynamicSharedMemorySize, SMOOTH_DSMEM);
    setup_kernel<<<1, 32>>>(params);
    tin_kernel<<<NCH * 128, 1024>>>(tracks);
    biquad_kernel<<<NCH, K_CHUNK>>>();
    prep_kernel<<<1024, 1024>>>();
    compose_kernel<<<(NGRP * NCH) / 256, 256>>>();
    smooth_serial<<<1, 32, SMOOTH_DSMEM>>>();
    finish_kernel<<<(NGRP * NB + 255) / 256, 256>>>((float*)d_out);
}